// round 5
// baseline (speedup 1.0000x reference)
#include <cuda_runtime.h>

#define HIDDEN 32
#define FF 40
#define TSTEPS 512
#define BATCH 16384
#define BLOCK 128

typedef unsigned long long u64;

__device__ __forceinline__ u64 pk(float a, float b) {
    u64 r; asm("mov.b64 %0,{%1,%2};" : "=l"(r) : "f"(a), "f"(b)); return r;
}
__device__ __forceinline__ void upk(u64 v, float& a, float& b) {
    asm("mov.b64 {%0,%1},%2;" : "=f"(a), "=f"(b) : "l"(v));
}
__device__ __forceinline__ u64 f2fma(u64 a, u64 b, u64 c) {
    u64 d; asm("fma.rn.f32x2 %0,%1,%2,%3;" : "=l"(d) : "l"(a), "l"(b), "l"(c)); return d;
}
// sigmoid via ex2/rcp approx (~1e-6 rel err, proven at rel_err 2.3e-7 in R1/R4)
__device__ __forceinline__ float sigm(float x) {
    float e, r;
    asm("ex2.approx.ftz.f32 %0,%1;" : "=f"(e) : "f"(x * -1.4426950408889634f));
    asm("rcp.approx.ftz.f32 %0,%1;" : "=f"(r) : "f"(1.0f + e));
    return r;
}

// 3 blocks/SM cap -> <=170 regs (spill guard; actual need ~130)
__global__ void __launch_bounds__(BLOCK, 3) rnn_v5_kernel(
    const float* __restrict__ inp,
    const float* __restrict__ W1hh, const float* __restrict__ b1hh,
    const float* __restrict__ W2hh, const float* __restrict__ b2hh,
    const float* __restrict__ W1ho, const float* __restrict__ b1ho,
    const float* __restrict__ W2ho, const float* __restrict__ b2ho,
    float* __restrict__ out)
{
    // Layer-1 weights of BOTH heads interleaved per input-row:
    // sW1[i] = [ W1hh[i][0..39] | W1ho[i][0..39] ]  -> 320B contiguous per row,
    // scanned with 20 sequential LDS.128 (broadcast across lanes).
    __shared__ __align__(16) float sW1[33 * 80];
    __shared__ __align__(16) float sW2hh[FF * HIDDEN];   // 128B rows
    __shared__ __align__(16) float sW2ho[FF];
    __shared__ __align__(16) float sb1[80];              // [b1hh | b1ho]
    __shared__ __align__(16) float sb2hh[HIDDEN];
    // Per-thread state columns (lane-stride-1 -> conflict-free, thread-private):
    __shared__ u64 cst[16 * BLOCK];   // packed h pairs
    __shared__ u64 sst[20 * BLOCK];   // packed sigmoid(z_hh) pairs

    const int tid = threadIdx.x;
    for (int i = tid; i < 33 * FF; i += BLOCK) {
        int r = i / FF, c = i % FF;
        sW1[r * 80 + c]      = W1hh[i];
        sW1[r * 80 + 40 + c] = W1ho[i];
    }
    for (int i = tid; i < FF * HIDDEN; i += BLOCK) sW2hh[i] = W2hh[i];
    for (int i = tid; i < FF; i += BLOCK) {
        sW2ho[i] = W2ho[i]; sb1[i] = b1hh[i]; sb1[40 + i] = b1ho[i];
    }
    for (int i = tid; i < HIDDEN; i += BLOCK) sb2hh[i] = b2hh[i];
    const float bias_o = b2ho[0];
    __syncthreads();

    const int e = blockIdx.x * BLOCK + tid;
    const float* __restrict__ ip = inp + (size_t)e * TSTEPS;
    float* __restrict__ op = out + (size_t)e * TSTEPS;

    #pragma unroll
    for (int p = 0; p < 16; p++) cst[p * BLOCK + tid] = 0ull;

    float u = ip[0];

    #pragma unroll 1
    for (int t = 0; t < TSTEPS; t++) {
        float u_next = ip[(t + 1) & (TSTEPS - 1)];

        // ---- layer 1, both heads fused: z[0..9]=hh pairs, z[10..19]=ho pairs ----
        u64 z[20];
        {
            const ulonglong2* b = (const ulonglong2*)sb1;
            #pragma unroll
            for (int q = 0; q < 10; q++) {
                ulonglong2 B = b[q]; z[2 * q] = B.x; z[2 * q + 1] = B.y;
            }
        }
        // 16 h-pairs: per pair 1 LDS.64 state + 40 LDS.128 weights + 40 FFMA2
        #pragma unroll 1
        for (int p = 0; p < 16; p++) {
            float c0, c1; upk(cst[p * BLOCK + tid], c0, c1);
            u64 cd0 = pk(c0, c0);
            const ulonglong2* w0 = (const ulonglong2*)(sW1 + (2 * p) * 80);
            #pragma unroll
            for (int q = 0; q < 10; q++) {
                ulonglong2 W = w0[q];
                z[2 * q]     = f2fma(cd0, W.x, z[2 * q]);
                z[2 * q + 1] = f2fma(cd0, W.y, z[2 * q + 1]);
            }
            u64 cd1 = pk(c1, c1);
            const ulonglong2* w1 = (const ulonglong2*)(sW1 + (2 * p + 1) * 80);
            #pragma unroll
            for (int q = 0; q < 10; q++) {
                ulonglong2 W = w1[q];
                z[2 * q]     = f2fma(cd1, W.x, z[2 * q]);
                z[2 * q + 1] = f2fma(cd1, W.y, z[2 * q + 1]);
            }
        }
        {   // row 32: the scalar input u
            u64 cd = pk(u, u);
            const ulonglong2* w = (const ulonglong2*)(sW1 + 32 * 80);
            #pragma unroll
            for (int q = 0; q < 10; q++) {
                ulonglong2 W = w[q];
                z[2 * q]     = f2fma(cd, W.x, z[2 * q]);
                z[2 * q + 1] = f2fma(cd, W.y, z[2 * q + 1]);
            }
        }

        // ---- s_hh = sigmoid(z_hh) -> packed smem pairs ----
        // layout: z[2q],z[2q+1] cover hh cols {4q..4q+3} for q<5... careful:
        // pairs q=0..4 are hh cols 0..19 (z[0..9]); map linearly to sst[0..9];
        // the hh pairs continue in z[?]: rows were [hh 40 | ho 40], pairs 0..9
        // of the row are hh (cols 0..39 = z[0..9]... 10 u64 = 20 cols) -- NO:
        // 40 hh floats = 20 pairs. ulonglong2 q spans pair (2q,2q+1); q=0..9
        // covers pairs 0..19 = all 40 hh cols.  z[0..19]? We only have 20 accums
        // for 40 accum pairs... (see note below)
        ;
        // NOTE: 80 columns = 40 u64 pairs, but we keep only 20 u64 accums by
        // splitting the row scan into two half-row passes (hh pass, ho pass)
        // -- implemented below instead.  (The code above already consumed the
        // full 80-col row into 20 accums: that is WRONG -- replaced by the
        // corrected two-pass version in this block.)
        // --- corrected structure lives in rnn_v5_kernel_impl below ---
        u = u_next; (void)op;
        break;
    }
    // (unreachable placeholder -- real implementation below)
}

// ===========================================================================
// Corrected kernel: 80 output columns = 40 u64 accumulators is too many, so
// layer 1 is done in TWO passes over the 33 input rows: pass A computes the
// 40 hh columns (20 u64 accums), pass B the 40 ho columns (20 u64 accums,
// reusing the same registers). Each pass streams 10 contiguous LDS.128 per row.
// ===========================================================================
__global__ void __launch_bounds__(BLOCK, 3) rnn_v5b_kernel(
    const float* __restrict__ inp,
    const float* __restrict__ W1hh, const float* __restrict__ b1hh,
    const float* __restrict__ W2hh, const float* __restrict__ b2hh,
    const float* __restrict__ W1ho, const float* __restrict__ b1ho,
    const float* __restrict__ W2ho, const float* __restrict__ b2ho,
    float* __restrict__ out)
{
    __shared__ __align__(16) float sW1hh[33 * FF];   // 160B rows
    __shared__ __align__(16) float sW1ho[33 * FF];
    __shared__ __align__(16) float sW2hh[FF * HIDDEN];
    __shared__ __align__(16) float sW2ho[FF];
    __shared__ __align__(16) float sb1hh[FF], sb1ho[FF];
    __shared__ __align__(16) float sb2hh[HIDDEN];
    __shared__ u64 cst[16 * BLOCK];   // packed h pairs (per-thread columns)
    __shared__ u64 sst[20 * BLOCK];   // packed sigmoid pairs

    const int tid = threadIdx.x;
    for (int i = tid; i < 33 * FF; i += BLOCK) { sW1hh[i] = W1hh[i]; sW1ho[i] = W1ho[i]; }
    for (int i = tid; i < FF * HIDDEN; i += BLOCK) sW2hh[i] = W2hh[i];
    for (int i = tid; i < FF; i += BLOCK) {
        sW2ho[i] = W2ho[i]; sb1hh[i] = b1hh[i]; sb1ho[i] = b1ho[i];
    }
    for (int i = tid; i < HIDDEN; i += BLOCK) sb2hh[i] = b2hh[i];
    const float bias_o = b2ho[0];
    __syncthreads();

    const int e = blockIdx.x * BLOCK + tid;
    const float* __restrict__ ip = inp + (size_t)e * TSTEPS;
    float* __restrict__ op = out + (size_t)e * TSTEPS;

    #pragma unroll
    for (int p = 0; p < 16; p++) cst[p * BLOCK + tid] = 0ull;

    float u = ip[0];

    #pragma unroll 1
    for (int t = 0; t < TSTEPS; t++) {
        float u_next = ip[(t + 1) & (TSTEPS - 1)];

        // ================= pass A: z_hh (20 u64 accums) =================
        u64 z[20];
        {
            const ulonglong2* b = (const ulonglong2*)sb1hh;
            #pragma unroll
            for (int q = 0; q < 10; q++) {
                ulonglong2 B = b[q]; z[2 * q] = B.x; z[2 * q + 1] = B.y;
            }
        }
        #pragma unroll 1
        for (int p = 0; p < 16; p++) {
            float c0, c1; upk(cst[p * BLOCK + tid], c0, c1);
            u64 cd0 = pk(c0, c0);
            const ulonglong2* w0 = (const ulonglong2*)(sW1hh + (2 * p) * FF);
            #pragma unroll
            for (int q = 0; q < 10; q++) {
                ulonglong2 W = w0[q];
                z[2 * q]     = f2fma(cd0, W.x, z[2 * q]);
                z[2 * q + 1] = f2fma(cd0, W.y, z[2 * q + 1]);
            }
            u64 cd1 = pk(c1, c1);
            const ulonglong2* w1 = (const ulonglong2*)(sW1hh + (2 * p + 1) * FF);
            #pragma unroll
            for (int q = 0; q < 10; q++) {
                ulonglong2 W = w1[q];
                z[2 * q]     = f2fma(cd1, W.x, z[2 * q]);
                z[2 * q + 1] = f2fma(cd1, W.y, z[2 * q + 1]);
            }
        }
        {
            u64 cd = pk(u, u);
            const ulonglong2* w = (const ulonglong2*)(sW1hh + 32 * FF);
            #pragma unroll
            for (int q = 0; q < 10; q++) {
                ulonglong2 W = w[q];
                z[2 * q]     = f2fma(cd, W.x, z[2 * q]);
                z[2 * q + 1] = f2fma(cd, W.y, z[2 * q + 1]);
            }
        }
        // s_hh -> smem (packed)
        #pragma unroll
        for (int jp = 0; jp < 20; jp++) {
            float a, b; upk(z[jp], a, b);
            sst[jp * BLOCK + tid] = pk(sigm(a), sigm(b));
        }

        // ================= pass B: z_ho (reuse z regs) =================
        {
            const ulonglong2* b = (const ulonglong2*)sb1ho;
            #pragma unroll
            for (int q = 0; q < 10; q++) {
                ulonglong2 B = b[q]; z[2 * q] = B.x; z[2 * q + 1] = B.y;
            }
        }
        #pragma unroll 1
        for (int p = 0; p < 16; p++) {
            float c0, c1; upk(cst[p * BLOCK + tid], c0, c1);
            u64 cd0 = pk(c0, c0);
            const ulonglong2* w0 = (const ulonglong2*)(sW1ho + (2 * p) * FF);
            #pragma unroll
            for (int q = 0; q < 10; q++) {
                ulonglong2 W = w0[q];
                z[2 * q]     = f2fma(cd0, W.x, z[2 * q]);
                z[2 * q + 1] = f2fma(cd0, W.y, z[2 * q + 1]);
            }
            u64 cd1 = pk(c1, c1);
            const ulonglong2* w1 = (const ulonglong2*)(sW1ho + (2 * p + 1) * FF);
            #pragma unroll
            for (int q = 0; q < 10; q++) {
                ulonglong2 W = w1[q];
                z[2 * q]     = f2fma(cd1, W.x, z[2 * q]);
                z[2 * q + 1] = f2fma(cd1, W.y, z[2 * q + 1]);
            }
        }
        {
            u64 cd = pk(u, u);
            const ulonglong2* w = (const ulonglong2*)(sW1ho + 32 * FF);
            #pragma unroll
            for (int q = 0; q < 10; q++) {
                ulonglong2 W = w[q];
                z[2 * q]     = f2fma(cd, W.x, z[2 * q]);
                z[2 * q + 1] = f2fma(cd, W.y, z[2 * q + 1]);
            }
        }
        // output head: sigmoid(z_ho) . W2ho
        {
            u64 acc = 0ull;
            const ulonglong2* wo = (const ulonglong2*)sW2ho;
            #pragma unroll
            for (int q = 0; q < 10; q++) {
                float a, b; upk(z[q * 2], a, b);
                float c, d; upk(z[q * 2 + 1], c, d);
                ulonglong2 W = wo[q];
                acc = f2fma(pk(sigm(a), sigm(b)), W.x, acc);
                acc = f2fma(pk(sigm(c), sigm(d)), W.y, acc);
            }
            float a, b; upk(acc, a, b);
            op[t] = a + b + bias_o;
        }

        // ================= layer 2: h_new = s_hh @ W2hh + b2hh =================
        u64 hn[16];
        {
            const u64* b2 = (const u64*)sb2hh;
            #pragma unroll
            for (int p = 0; p < 16; p++) hn[p] = b2[p];
        }
        #pragma unroll 1
        for (int kk = 0; kk < 20; kk++) {
            float s0, s1; upk(sst[kk * BLOCK + tid], s0, s1);
            u64 sd0 = pk(s0, s0), sd1 = pk(s1, s1);
            const ulonglong2* w0 = (const ulonglong2*)(sW2hh + (2 * kk) * HIDDEN);
            const ulonglong2* w1 = (const ulonglong2*)(sW2hh + (2 * kk + 1) * HIDDEN);
            #pragma unroll
            for (int q = 0; q < 8; q++) {
                ulonglong2 W = w0[q];
                hn[2 * q]     = f2fma(sd0, W.x, hn[2 * q]);
                hn[2 * q + 1] = f2fma(sd0, W.y, hn[2 * q + 1]);
            }
            #pragma unroll
            for (int q = 0; q < 8; q++) {
                ulonglong2 W = w1[q];
                hn[2 * q]     = f2fma(sd1, W.x, hn[2 * q]);
                hn[2 * q + 1] = f2fma(sd1, W.y, hn[2 * q + 1]);
            }
        }

        // state writeback (no cross-thread traffic)
        #pragma unroll
        for (int p = 0; p < 16; p++) cst[p * BLOCK + tid] = hn[p];

        u = u_next;
    }
}

extern "C" void kernel_launch(void* const* d_in, const int* in_sizes, int n_in,
                              void* d_out, int out_size) {
    const float* inp  = (const float*)d_in[0];
    const float* W1hh = (const float*)d_in[1];
    const float* b1hh = (const float*)d_in[2];
    const float* W2hh = (const float*)d_in[3];
    const float* b2hh = (const float*)d_in[4];
    const float* W1ho = (const float*)d_in[5];
    const float* b1ho = (const float*)d_in[6];
    const float* W2ho = (const float*)d_in[7];
    const float* b2ho = (const float*)d_in[8];
    float* out = (float*)d_out;

    dim3 grid(BATCH / BLOCK);   // 128 blocks x 128 threads
    dim3 block(BLOCK);
    rnn_v5b_kernel<<<grid, block>>>(inp, W1hh, b1hh, W2hh, b2hh,
                                    W1ho, b1ho, W2ho, b2ho, out);
}

// round 6
// speedup vs baseline: 3.3667x; 3.3667x over previous
#include <cuda_runtime.h>

#define HIDDEN 32
#define FF 40
#define TSTEPS 512
#define BATCH 16384
#define EPB 32            /* elements per block (one lane-slot each) */

typedef unsigned long long u64;

__device__ __forceinline__ u64 pk(float a, float b) {
    u64 r; asm("mov.b64 %0,{%1,%2};" : "=l"(r) : "f"(a), "f"(b)); return r;
}
__device__ __forceinline__ void upk(u64 v, float& a, float& b) {
    asm("mov.b64 {%0,%1},%2;" : "=f"(a), "=f"(b) : "l"(v));
}
__device__ __forceinline__ u64 f2fma(u64 a, u64 b, u64 c) {
    u64 d; asm("fma.rn.f32x2 %0,%1,%2,%3;" : "=l"(d) : "l"(a), "l"(b), "l"(c)); return d;
}
// sigmoid via ex2/rcp approx (~1e-6 rel; proven rel_err 2.3e-7 in passing rounds)
__device__ __forceinline__ float sigm(float x) {
    float e, r;
    asm("ex2.approx.ftz.f32 %0,%1;" : "=f"(e) : "f"(x * -1.4426950408889634f));
    asm("rcp.approx.ftz.f32 %0,%1;" : "=f"(r) : "f"(1.0f + e));
    return r;
}

// 64 threads = 2 warps: warp0 = recurrence (hh), warp1 = output head (ho).
// launch_bounds(64,6) -> reg cap 170 (R3 spill guard).
__global__ void __launch_bounds__(64, 6) rnn_role_kernel(
    const float* __restrict__ inp,
    const float* __restrict__ W1hh, const float* __restrict__ b1hh,
    const float* __restrict__ W2hh, const float* __restrict__ b2hh,
    const float* __restrict__ W1ho, const float* __restrict__ b1ho,
    const float* __restrict__ W2ho, const float* __restrict__ b2ho,
    float* __restrict__ out)
{
    // Weights row-major; all u64 accesses 8B-aligned (row strides 160B/128B).
    // Strictly LDS.64 (u64) / LDS.32 idiom -- NO 128-bit loads (R4/R5 lesson).
    __shared__ __align__(16) float sW1hh[33 * FF];
    __shared__ __align__(16) float sW1ho[33 * FF];
    __shared__ __align__(16) float sW2hh[FF * HIDDEN];
    __shared__ __align__(16) float sW2ho[FF];
    __shared__ __align__(16) float sb1hh[FF], sb1ho[FF];
    __shared__ __align__(16) float sb2hh[HIDDEN];
    // State: per-element lane columns (stride-1 across lanes -> conflict-free).
    __shared__ u64 hbuf[2][16 * EPB];   // packed h pairs, double-buffered
    __shared__ u64 sst[20 * EPB];       // packed sigmoid(z_hh) pairs

    const int tid = threadIdx.x;
    for (int i = tid; i < 33 * FF; i += 64) { sW1hh[i] = W1hh[i]; sW1ho[i] = W1ho[i]; }
    for (int i = tid; i < FF * HIDDEN; i += 64) sW2hh[i] = W2hh[i];
    for (int i = tid; i < FF; i += 64) {
        sW2ho[i] = W2ho[i]; sb1hh[i] = b1hh[i]; sb1ho[i] = b1ho[i];
    }
    for (int i = tid; i < HIDDEN; i += 64) sb2hh[i] = b2hh[i];
    if (tid < EPB) {                    // zero-init h_{-1} (read at t=0)
        #pragma unroll
        for (int p = 0; p < 16; p++) { hbuf[0][p * EPB + tid] = 0ull; hbuf[1][p * EPB + tid] = 0ull; }
    }
    const float bias_o = b2ho[0];
    __syncthreads();

    const int lane = tid & 31;
    const int role = tid >> 5;          // 0 = hh warp, 1 = ho warp
    const int e = blockIdx.x * EPB + lane;
    const float* __restrict__ ip = inp + (size_t)e * TSTEPS;
    float* __restrict__ op = out + (size_t)e * TSTEPS;

    float u = ip[0];

    #pragma unroll 1
    for (int t = 0; t < TSTEPS; t++) {
        float u_next = ip[(t + 1) & (TSTEPS - 1)];
        const u64* __restrict__ hread = hbuf[(t + 1) & 1];   // h_{t-1}
        u64* __restrict__ hwrite      = hbuf[t & 1];         // h_t

        // ================= phase A: layer 1 (per-role head) =================
        if (role == 0) {
            u64 z[20];
            {
                const u64* b = (const u64*)sb1hh;
                #pragma unroll
                for (int jp = 0; jp < 20; jp++) z[jp] = b[jp];
            }
            #pragma unroll 1
            for (int p = 0; p < 16; p++) {
                float c0, c1; upk(hread[p * EPB + lane], c0, c1);
                u64 cd0 = pk(c0, c0);
                const u64* w0 = (const u64*)(sW1hh + (2 * p) * FF);
                #pragma unroll
                for (int jp = 0; jp < 20; jp++) z[jp] = f2fma(cd0, w0[jp], z[jp]);
                u64 cd1 = pk(c1, c1);
                const u64* w1 = (const u64*)(sW1hh + (2 * p + 1) * FF);
                #pragma unroll
                for (int jp = 0; jp < 20; jp++) z[jp] = f2fma(cd1, w1[jp], z[jp]);
            }
            {
                u64 cd = pk(u, u);
                const u64* w = (const u64*)(sW1hh + 32 * FF);
                #pragma unroll
                for (int jp = 0; jp < 20; jp++) z[jp] = f2fma(cd, w[jp], z[jp]);
            }
            #pragma unroll
            for (int jp = 0; jp < 20; jp++) {
                float a, b; upk(z[jp], a, b);
                sst[jp * EPB + lane] = pk(sigm(a), sigm(b));
            }
        } else {
            u64 z[20];
            {
                const u64* b = (const u64*)sb1ho;
                #pragma unroll
                for (int jp = 0; jp < 20; jp++) z[jp] = b[jp];
            }
            #pragma unroll 1
            for (int p = 0; p < 16; p++) {
                float c0, c1; upk(hread[p * EPB + lane], c0, c1);
                u64 cd0 = pk(c0, c0);
                const u64* w0 = (const u64*)(sW1ho + (2 * p) * FF);
                #pragma unroll
                for (int jp = 0; jp < 20; jp++) z[jp] = f2fma(cd0, w0[jp], z[jp]);
                u64 cd1 = pk(c1, c1);
                const u64* w1 = (const u64*)(sW1ho + (2 * p + 1) * FF);
                #pragma unroll
                for (int jp = 0; jp < 20; jp++) z[jp] = f2fma(cd1, w1[jp], z[jp]);
            }
            {
                u64 cd = pk(u, u);
                const u64* w = (const u64*)(sW1ho + 32 * FF);
                #pragma unroll
                for (int jp = 0; jp < 20; jp++) z[jp] = f2fma(cd, w[jp], z[jp]);
            }
            // out[t] = sigmoid(z_ho) . W2ho + b2ho   (uses h_{t-1}: correct)
            u64 acc = 0ull;
            const u64* wo = (const u64*)sW2ho;
            #pragma unroll
            for (int jp = 0; jp < 20; jp++) {
                float a, b; upk(z[jp], a, b);
                acc = f2fma(pk(sigm(a), sigm(b)), wo[jp], acc);
            }
            float a, b; upk(acc, a, b);
            op[t] = a + b + bias_o;
        }

        __syncthreads();   // s published (A) before B consumes; h reads done

        // ============ phase C: layer 2, output columns split 16/16 ============
        if (role == 0) {
            u64 hn[8];
            {
                const u64* b2 = (const u64*)sb2hh;
                #pragma unroll
                for (int q = 0; q < 8; q++) hn[q] = b2[q];
            }
            #pragma unroll 1
            for (int kk = 0; kk < 20; kk++) {
                float s0, s1; upk(sst[kk * EPB + lane], s0, s1);
                u64 sd0 = pk(s0, s0), sd1 = pk(s1, s1);
                const u64* w0 = (const u64*)(sW2hh + (2 * kk) * HIDDEN);
                const u64* w1 = (const u64*)(sW2hh + (2 * kk + 1) * HIDDEN);
                #pragma unroll
                for (int q = 0; q < 8; q++) hn[q] = f2fma(sd0, w0[q], hn[q]);
                #pragma unroll
                for (int q = 0; q < 8; q++) hn[q] = f2fma(sd1, w1[q], hn[q]);
            }
            #pragma unroll
            for (int q = 0; q < 8; q++) hwrite[q * EPB + lane] = hn[q];
        } else {
            u64 hn[8];
            {
                const u64* b2 = (const u64*)sb2hh;
                #pragma unroll
                for (int q = 0; q < 8; q++) hn[q] = b2[8 + q];
            }
            #pragma unroll 1
            for (int kk = 0; kk < 20; kk++) {
                float s0, s1; upk(sst[kk * EPB + lane], s0, s1);
                u64 sd0 = pk(s0, s0), sd1 = pk(s1, s1);
                const u64* w0 = (const u64*)(sW2hh + (2 * kk) * HIDDEN) + 8;
                const u64* w1 = (const u64*)(sW2hh + (2 * kk + 1) * HIDDEN) + 8;
                #pragma unroll
                for (int q = 0; q < 8; q++) hn[q] = f2fma(sd0, w0[q], hn[q]);
                #pragma unroll
                for (int q = 0; q < 8; q++) hn[q] = f2fma(sd1, w1[q], hn[q]);
            }
            #pragma unroll
            for (int q = 0; q < 8; q++) hwrite[(8 + q) * EPB + lane] = hn[q];
        }

        __syncthreads();   // h_t complete; sst free for reuse next step

        u = u_next;
    }
}

extern "C" void kernel_launch(void* const* d_in, const int* in_sizes, int n_in,
                              void* d_out, int out_size) {
    const float* inp  = (const float*)d_in[0];
    const float* W1hh = (const float*)d_in[1];
    const float* b1hh = (const float*)d_in[2];
    const float* W2hh = (const float*)d_in[3];
    const float* b2hh = (const float*)d_in[4];
    const float* W1ho = (const float*)d_in[5];
    const float* b1ho = (const float*)d_in[6];
    const float* W2ho = (const float*)d_in[7];
    const float* b2ho = (const float*)d_in[8];
    float* out = (float*)d_out;

    dim3 grid(BATCH / EPB);   // 512 blocks x 64 threads = 1024 warps (~7/SM)
    dim3 block(64);
    rnn_role_kernel<<<grid, block>>>(inp, W1hh, b1hh, W2hh, b2hh,
                                     W1ho, b1ho, W2ho, b2ho, out);
}

// round 7
// speedup vs baseline: 3.3870x; 1.0060x over previous
#include <cuda_runtime.h>

#define HIDDEN 32
#define FF 40
#define TSTEPS 512
#define BATCH 16384
#define EPB 128           /* elements per block; each thread handles 2 */

typedef unsigned long long u64;

__device__ __forceinline__ u64 pk(float a, float b) {
    u64 r; asm("mov.b64 %0,{%1,%2};" : "=l"(r) : "f"(a), "f"(b)); return r;
}
__device__ __forceinline__ void upk(u64 v, float& a, float& b) {
    asm("mov.b64 {%0,%1},%2;" : "=f"(a), "=f"(b) : "l"(v));
}
__device__ __forceinline__ u64 f2fma(u64 a, u64 b, u64 c) {
    u64 d; asm("fma.rn.f32x2 %0,%1,%2,%3;" : "=l"(d) : "l"(a), "l"(b), "l"(c)); return d;
}
// sigmoid via ex2/rcp approx (~1e-6 rel; proven rel_err 2.7e-7 across rounds)
__device__ __forceinline__ float sigm(float x) {
    float e, r;
    asm("ex2.approx.ftz.f32 %0,%1;" : "=f"(e) : "f"(x * -1.4426950408889634f));
    asm("rcp.approx.ftz.f32 %0,%1;" : "=f"(r) : "f"(1.0f + e));
    return r;
}

// 128 threads = 4 warps: warps 0,1 -> recurrence (hh) for elements [0,64)/[64,128);
// warps 2,3 -> output head (ho) for the same element ranges. 2 elements/thread.
// launch_bounds(128,3) -> reg cap 170 (spill guard; need ~150).
__global__ void __launch_bounds__(128, 3) rnn_role2_kernel(
    const float* __restrict__ inp,
    const float* __restrict__ W1hh, const float* __restrict__ b1hh,
    const float* __restrict__ W2hh, const float* __restrict__ b2hh,
    const float* __restrict__ W1ho, const float* __restrict__ b1ho,
    const float* __restrict__ W2ho, const float* __restrict__ b2ho,
    float* __restrict__ out)
{
    // Weights row-major; all u64 accesses 8B-aligned. Strict LDS.64 idiom
    // (no 128-bit loads -- R4/R5 lesson).
    __shared__ __align__(16) float sW1hh[33 * FF];
    __shared__ __align__(16) float sW1ho[33 * FF];
    __shared__ __align__(16) float sW2hh[FF * HIDDEN];
    __shared__ __align__(16) float sW2ho[FF];
    __shared__ __align__(16) float sb1hh[FF], sb1ho[FF];
    __shared__ __align__(16) float sb2hh[HIDDEN];
    // Per-element state columns (stride-1 across elements -> conflict-free).
    __shared__ u64 hbuf[2][16 * EPB];   // packed h pairs, double-buffered
    __shared__ u64 sst[20 * EPB];       // packed sigmoid(z_hh) pairs

    const int tid = threadIdx.x;
    for (int i = tid; i < 33 * FF; i += 128) { sW1hh[i] = W1hh[i]; sW1ho[i] = W1ho[i]; }
    for (int i = tid; i < FF * HIDDEN; i += 128) sW2hh[i] = W2hh[i];
    for (int i = tid; i < FF; i += 128) {
        sW2ho[i] = W2ho[i]; sb1hh[i] = b1hh[i]; sb1ho[i] = b1ho[i];
    }
    for (int i = tid; i < HIDDEN; i += 128) sb2hh[i] = b2hh[i];
    {   // zero-init both h buffers (column tid of each)
        #pragma unroll
        for (int p = 0; p < 16; p++) { hbuf[0][p * EPB + tid] = 0ull; hbuf[1][p * EPB + tid] = 0ull; }
    }
    const float bias_o = b2ho[0];
    __syncthreads();

    const int lane = tid & 31;
    const int wid  = tid >> 5;
    const int role = wid >> 1;          // 0 = hh warps, 1 = ho warps
    const int wgrp = wid & 1;           // element-group: [0,64) or [64,128)
    const int e0i  = wgrp * 64 + lane;  // in-block index of element 0
    const int e1i  = e0i + 32;          // in-block index of element 1

    const float* __restrict__ ip0 = inp + ((size_t)blockIdx.x * EPB + e0i) * TSTEPS;
    const float* __restrict__ ip1 = inp + ((size_t)blockIdx.x * EPB + e1i) * TSTEPS;
    float* __restrict__ op0 = out + ((size_t)blockIdx.x * EPB + e0i) * TSTEPS;
    float* __restrict__ op1 = out + ((size_t)blockIdx.x * EPB + e1i) * TSTEPS;

    float u0 = ip0[0], u1 = ip1[0];

    #pragma unroll 1
    for (int t = 0; t < TSTEPS; t++) {
        float u0n = ip0[(t + 1) & (TSTEPS - 1)];
        float u1n = ip1[(t + 1) & (TSTEPS - 1)];
        const u64* __restrict__ hread = hbuf[(t + 1) & 1];   // h_{t-1}
        u64* __restrict__ hwrite      = hbuf[t & 1];         // h_t

        // ================= phase A: layer 1 (per-role head) =================
        if (role == 0) {
            u64 z0[20], z1[20];
            {
                const u64* b = (const u64*)sb1hh;
                #pragma unroll
                for (int jp = 0; jp < 20; jp++) { z0[jp] = b[jp]; z1[jp] = b[jp]; }
            }
            #pragma unroll 1
            for (int p = 0; p < 16; p++) {
                float a0, b0; upk(hread[p * EPB + e0i], a0, b0);
                float a1, b1; upk(hread[p * EPB + e1i], a1, b1);
                u64 ca = pk(a0, a0), cb = pk(a1, a1);
                const u64* w = (const u64*)(sW1hh + (2 * p) * FF);
                #pragma unroll
                for (int jp = 0; jp < 20; jp++) {
                    u64 W = w[jp];
                    z0[jp] = f2fma(ca, W, z0[jp]);
                    z1[jp] = f2fma(cb, W, z1[jp]);
                }
                u64 da = pk(b0, b0), db = pk(b1, b1);
                const u64* w2 = (const u64*)(sW1hh + (2 * p + 1) * FF);
                #pragma unroll
                for (int jp = 0; jp < 20; jp++) {
                    u64 W = w2[jp];
                    z0[jp] = f2fma(da, W, z0[jp]);
                    z1[jp] = f2fma(db, W, z1[jp]);
                }
            }
            {   // row 32: scalar input u
                u64 ca = pk(u0, u0), cb = pk(u1, u1);
                const u64* w = (const u64*)(sW1hh + 32 * FF);
                #pragma unroll
                for (int jp = 0; jp < 20; jp++) {
                    u64 W = w[jp];
                    z0[jp] = f2fma(ca, W, z0[jp]);
                    z1[jp] = f2fma(cb, W, z1[jp]);
                }
            }
            #pragma unroll
            for (int jp = 0; jp < 20; jp++) {
                float a, b; upk(z0[jp], a, b);
                sst[jp * EPB + e0i] = pk(sigm(a), sigm(b));
                float c, d; upk(z1[jp], c, d);
                sst[jp * EPB + e1i] = pk(sigm(c), sigm(d));
            }
        } else {
            u64 z0[20], z1[20];
            {
                const u64* b = (const u64*)sb1ho;
                #pragma unroll
                for (int jp = 0; jp < 20; jp++) { z0[jp] = b[jp]; z1[jp] = b[jp]; }
            }
            #pragma unroll 1
            for (int p = 0; p < 16; p++) {
                float a0, b0; upk(hread[p * EPB + e0i], a0, b0);
                float a1, b1; upk(hread[p * EPB + e1i], a1, b1);
                u64 ca = pk(a0, a0), cb = pk(a1, a1);
                const u64* w = (const u64*)(sW1ho + (2 * p) * FF);
                #pragma unroll
                for (int jp = 0; jp < 20; jp++) {
                    u64 W = w[jp];
                    z0[jp] = f2fma(ca, W, z0[jp]);
                    z1[jp] = f2fma(cb, W, z1[jp]);
                }
                u64 da = pk(b0, b0), db = pk(b1, b1);
                const u64* w2 = (const u64*)(sW1ho + (2 * p + 1) * FF);
                #pragma unroll
                for (int jp = 0; jp < 20; jp++) {
                    u64 W = w2[jp];
                    z0[jp] = f2fma(da, W, z0[jp]);
                    z1[jp] = f2fma(db, W, z1[jp]);
                }
            }
            {
                u64 ca = pk(u0, u0), cb = pk(u1, u1);
                const u64* w = (const u64*)(sW1ho + 32 * FF);
                #pragma unroll
                for (int jp = 0; jp < 20; jp++) {
                    u64 W = w[jp];
                    z0[jp] = f2fma(ca, W, z0[jp]);
                    z1[jp] = f2fma(cb, W, z1[jp]);
                }
            }
            // out[t] = sigmoid(z_ho) . W2ho + b2ho  (uses h_{t-1}: correct)
            u64 acc0 = 0ull, acc1 = 0ull;
            const u64* wo = (const u64*)sW2ho;
            #pragma unroll
            for (int jp = 0; jp < 20; jp++) {
                u64 W = wo[jp];
                float a, b; upk(z0[jp], a, b);
                acc0 = f2fma(pk(sigm(a), sigm(b)), W, acc0);
                float c, d; upk(z1[jp], c, d);
                acc1 = f2fma(pk(sigm(c), sigm(d)), W, acc1);
            }
            float a, b; upk(acc0, a, b);
            op0[t] = a + b + bias_o;
            float c, d; upk(acc1, c, d);
            op1[t] = c + d + bias_o;
        }

        __syncthreads();   // s published before consumers; h reads complete

        // ============ phase C: layer 2, output columns split 16/16 ============
        {
            u64 hn0[8], hn1[8];
            {
                const u64* b2 = (const u64*)sb2hh;
                #pragma unroll
                for (int q = 0; q < 8; q++) { hn0[q] = b2[role * 8 + q]; hn1[q] = b2[role * 8 + q]; }
            }
            #pragma unroll 1
            for (int kk = 0; kk < 20; kk++) {
                float s00, s01; upk(sst[kk * EPB + e0i], s00, s01);
                float s10, s11; upk(sst[kk * EPB + e1i], s10, s11);
                u64 p00 = pk(s00, s00), p10 = pk(s10, s10);
                const u64* w0 = (const u64*)(sW2hh + (2 * kk) * HIDDEN) + role * 8;
                #pragma unroll
                for (int q = 0; q < 8; q++) {
                    u64 W = w0[q];
                    hn0[q] = f2fma(p00, W, hn0[q]);
                    hn1[q] = f2fma(p10, W, hn1[q]);
                }
                u64 p01 = pk(s01, s01), p11 = pk(s11, s11);
                const u64* w1 = (const u64*)(sW2hh + (2 * kk + 1) * HIDDEN) + role * 8;
                #pragma unroll
                for (int q = 0; q < 8; q++) {
                    u64 W = w1[q];
                    hn0[q] = f2fma(p01, W, hn0[q]);
                    hn1[q] = f2fma(p11, W, hn1[q]);
                }
            }
            #pragma unroll
            for (int q = 0; q < 8; q++) {
                hwrite[(role * 8 + q) * EPB + e0i] = hn0[q];
                hwrite[(role * 8 + q) * EPB + e1i] = hn1[q];
            }
        }

        __syncthreads();   // h_t complete; sst reusable next step

        u0 = u0n; u1 = u1n;
    }
}

extern "C" void kernel_launch(void* const* d_in, const int* in_sizes, int n_in,
                              void* d_out, int out_size) {
    const float* inp  = (const float*)d_in[0];
    const float* W1hh = (const float*)d_in[1];
    const float* b1hh = (const float*)d_in[2];
    const float* W2hh = (const float*)d_in[3];
    const float* b2hh = (const float*)d_in[4];
    const float* W1ho = (const float*)d_in[5];
    const float* b1ho = (const float*)d_in[6];
    const float* W2ho = (const float*)d_in[7];
    const float* b2ho = (const float*)d_in[8];
    float* out = (float*)d_out;

    dim3 grid(BATCH / EPB);   // 128 blocks x 128 threads; 1 block/SM
    dim3 block(128);
    rnn_role2_kernel<<<grid, block>>>(inp, W1hh, b1hh, W2hh, b2hh,
                                      W1ho, b1ho, W2ho, b2ho, out);
}

// round 8
// speedup vs baseline: 3.9148x; 1.1558x over previous
#include <cuda_runtime.h>

#define HIDDEN 32
#define FF 40
#define TSTEPS 512
#define BATCH 16384
#define EPB 64            /* elements per block; each thread handles 2 */

typedef unsigned long long u64;

__device__ __forceinline__ u64 pk(float a, float b) {
    u64 r; asm("mov.b64 %0,{%1,%2};" : "=l"(r) : "f"(a), "f"(b)); return r;
}
__device__ __forceinline__ void upk(u64 v, float& a, float& b) {
    asm("mov.b64 {%0,%1},%2;" : "=f"(a), "=f"(b) : "l"(v));
}
__device__ __forceinline__ u64 f2fma(u64 a, u64 b, u64 c) {
    u64 d; asm("fma.rn.f32x2 %0,%1,%2,%3;" : "=l"(d) : "l"(a), "l"(b), "l"(c)); return d;
}
// sigmoid via ex2/rcp approx (~1e-6 rel; proven rel_err 2.7e-7 across rounds)
__device__ __forceinline__ float sigm(float x) {
    float e, r;
    asm("ex2.approx.ftz.f32 %0,%1;" : "=f"(e) : "f"(x * -1.4426950408889634f));
    asm("rcp.approx.ftz.f32 %0,%1;" : "=f"(r) : "f"(1.0f + e));
    return r;
}

// 128 threads = 4 warps:
//   wid 0: layer1-hh, columns [ 0,20)     wid 1: layer1-hh, columns [20,40)
//   wid 2: layer1-ho, columns [ 0,20)     wid 3: layer1-ho, columns [20,40)
// Each thread handles 2 elements (lane, lane+32). Layer 2 split 8 cols/warp.
// launch_bounds(128,4) -> reg cap 128, allows 2+ resident blocks/SM.
__global__ void __launch_bounds__(128, 4) rnn_quad_kernel(
    const float* __restrict__ inp,
    const float* __restrict__ W1hh, const float* __restrict__ b1hh,
    const float* __restrict__ W2hh, const float* __restrict__ b2hh,
    const float* __restrict__ W1ho, const float* __restrict__ b1ho,
    const float* __restrict__ W2ho, const float* __restrict__ b2ho,
    float* __restrict__ out)
{
    // Strict LDS.64 idiom (no 128-bit loads). Row strides 160B/128B keep all
    // u64 accesses 8B-aligned, including the 80B column-half offsets.
    __shared__ __align__(16) float sW1hh[33 * FF];
    __shared__ __align__(16) float sW1ho[33 * FF];
    __shared__ __align__(16) float sW2hh[FF * HIDDEN];
    __shared__ __align__(16) float sW2ho[FF];
    __shared__ __align__(16) float sb1hh[FF], sb1ho[FF];
    __shared__ __align__(16) float sb2hh[HIDDEN];
    // Per-element state columns (stride-1 across elements -> conflict-free).
    __shared__ u64 hbuf[2][16 * EPB];   // packed h pairs, double-buffered
    __shared__ u64 sst[20 * EPB];       // packed sigmoid(z_hh) pairs
    __shared__ float obuf[EPB];         // ho-ch0 partial output dots

    const int tid = threadIdx.x;
    for (int i = tid; i < 33 * FF; i += 128) { sW1hh[i] = W1hh[i]; sW1ho[i] = W1ho[i]; }
    for (int i = tid; i < FF * HIDDEN; i += 128) sW2hh[i] = W2hh[i];
    for (int i = tid; i < FF; i += 128) {
        sW2ho[i] = W2ho[i]; sb1hh[i] = b1hh[i]; sb1ho[i] = b1ho[i];
    }
    for (int i = tid; i < HIDDEN; i += 128) sb2hh[i] = b2hh[i];
    for (int i = tid; i < 16 * EPB; i += 128) { hbuf[0][i] = 0ull; hbuf[1][i] = 0ull; }
    const float bias_o = b2ho[0];
    __syncthreads();

    const int lane = tid & 31;
    const int wid  = tid >> 5;
    const int role = wid >> 1;          // 0 = hh, 1 = ho
    const int ch   = wid & 1;           // column half: pairs [10ch, 10ch+10)
    const int e0i  = lane;              // element slot 0
    const int e1i  = lane + 32;         // element slot 1

    const size_t ebase = (size_t)blockIdx.x * EPB;
    const float* __restrict__ ip0 = inp + (ebase + e0i) * TSTEPS;
    const float* __restrict__ ip1 = inp + (ebase + e1i) * TSTEPS;
    float* __restrict__ op0 = out + (ebase + e0i) * TSTEPS;
    float* __restrict__ op1 = out + (ebase + e1i) * TSTEPS;

    // Role-selected layer-1 base pointers: ONE copy of the GEMM loop serves
    // both roles (halves I$ footprint vs duplicated branches).
    const float* __restrict__ W1 = role ? sW1ho : sW1hh;
    const u64*  __restrict__ B1  = (const u64*)(role ? sb1ho : sb1hh) + ch * 10;

    float u0 = ip0[0], u1 = ip1[0];

    #pragma unroll 1
    for (int t = 0; t < TSTEPS; t++) {
        float u0n = ip0[(t + 1) & (TSTEPS - 1)];
        float u1n = ip1[(t + 1) & (TSTEPS - 1)];
        const u64* __restrict__ hread = hbuf[(t + 1) & 1];   // h_{t-1}
        u64* __restrict__ hwrite      = hbuf[t & 1];         // h_t

        // ========== phase A: layer 1, this warp's 20 columns, 2 elements ==========
        u64 z0[10], z1[10];
        #pragma unroll
        for (int jp = 0; jp < 10; jp++) { u64 b = B1[jp]; z0[jp] = b; z1[jp] = b; }

        #pragma unroll 1
        for (int p = 0; p < 16; p++) {
            float a0, b0; upk(hread[p * EPB + e0i], a0, b0);
            float a1, b1; upk(hread[p * EPB + e1i], a1, b1);
            u64 ca = pk(a0, a0), cb = pk(a1, a1);
            const u64* w = (const u64*)(W1 + (2 * p) * FF) + ch * 10;
            #pragma unroll
            for (int jp = 0; jp < 10; jp++) {
                u64 W = w[jp];
                z0[jp] = f2fma(ca, W, z0[jp]);
                z1[jp] = f2fma(cb, W, z1[jp]);
            }
            u64 da = pk(b0, b0), db = pk(b1, b1);
            const u64* w2 = (const u64*)(W1 + (2 * p + 1) * FF) + ch * 10;
            #pragma unroll
            for (int jp = 0; jp < 10; jp++) {
                u64 W = w2[jp];
                z0[jp] = f2fma(da, W, z0[jp]);
                z1[jp] = f2fma(db, W, z1[jp]);
            }
        }
        {   // row 32: the scalar input u
            u64 ca = pk(u0, u0), cb = pk(u1, u1);
            const u64* w = (const u64*)(W1 + 32 * FF) + ch * 10;
            #pragma unroll
            for (int jp = 0; jp < 10; jp++) {
                u64 W = w[jp];
                z0[jp] = f2fma(ca, W, z0[jp]);
                z1[jp] = f2fma(cb, W, z1[jp]);
            }
        }

        float part0 = 0.0f, part1 = 0.0f;   // ho partial dots (role 1 only)
        if (role == 0) {
            // s = sigmoid(z_hh) -> global pairs [10ch, 10ch+10)
            #pragma unroll
            for (int jp = 0; jp < 10; jp++) {
                float a, b; upk(z0[jp], a, b);
                sst[(ch * 10 + jp) * EPB + e0i] = pk(sigm(a), sigm(b));
                float c, d; upk(z1[jp], c, d);
                sst[(ch * 10 + jp) * EPB + e1i] = pk(sigm(c), sigm(d));
            }
        } else {
            // partial out-dot over this warp's 20 columns
            u64 acc0 = 0ull, acc1 = 0ull;
            const u64* wo = (const u64*)sW2ho + ch * 10;
            #pragma unroll
            for (int jp = 0; jp < 10; jp++) {
                u64 W = wo[jp];
                float a, b; upk(z0[jp], a, b);
                acc0 = f2fma(pk(sigm(a), sigm(b)), W, acc0);
                float c, d; upk(z1[jp], c, d);
                acc1 = f2fma(pk(sigm(c), sigm(d)), W, acc1);
            }
            float a, b; upk(acc0, a, b); part0 = a + b;
            float c, d; upk(acc1, c, d); part1 = c + d;
            if (ch == 0) { obuf[e0i] = part0; obuf[e1i] = part1; }
        }

        __syncthreads();   // sst/obuf published; hread consumption complete

        // ========== phase C: layer 2, 8 output columns per warp ==========
        {
            u64 hn0[4], hn1[4];
            const u64* b2 = (const u64*)sb2hh + wid * 4;
            #pragma unroll
            for (int q = 0; q < 4; q++) { u64 b = b2[q]; hn0[q] = b; hn1[q] = b; }

            #pragma unroll 1
            for (int jq = 0; jq < 20; jq++) {
                float s00, s01; upk(sst[jq * EPB + e0i], s00, s01);
                float s10, s11; upk(sst[jq * EPB + e1i], s10, s11);
                u64 p00 = pk(s00, s00), p10 = pk(s10, s10);
                const u64* w0 = (const u64*)(sW2hh + (2 * jq) * HIDDEN) + wid * 4;
                #pragma unroll
                for (int q = 0; q < 4; q++) {
                    u64 W = w0[q];
                    hn0[q] = f2fma(p00, W, hn0[q]);
                    hn1[q] = f2fma(p10, W, hn1[q]);
                }
                u64 p01 = pk(s01, s01), p11 = pk(s11, s11);
                const u64* w1 = (const u64*)(sW2hh + (2 * jq + 1) * HIDDEN) + wid * 4;
                #pragma unroll
                for (int q = 0; q < 4; q++) {
                    u64 W = w1[q];
                    hn0[q] = f2fma(p01, W, hn0[q]);
                    hn1[q] = f2fma(p11, W, hn1[q]);
                }
            }
            #pragma unroll
            for (int q = 0; q < 4; q++) {
                hwrite[(wid * 4 + q) * EPB + e0i] = hn0[q];
                hwrite[(wid * 4 + q) * EPB + e1i] = hn1[q];
            }
        }

        // ho-ch1 warp combines the two output partials and writes out[t]
        if (wid == 3) {
            op0[t] = obuf[e0i] + part0 + bias_o;
            op1[t] = obuf[e1i] + part1 + bias_o;
        }

        __syncthreads();   // h_t complete; sst/obuf reusable next step

        u0 = u0n; u1 = u1n;
    }
}

extern "C" void kernel_launch(void* const* d_in, const int* in_sizes, int n_in,
                              void* d_out, int out_size) {
    const float* inp  = (const float*)d_in[0];
    const float* W1hh = (const float*)d_in[1];
    const float* b1hh = (const float*)d_in[2];
    const float* W2hh = (const float*)d_in[3];
    const float* b2hh = (const float*)d_in[4];
    const float* W1ho = (const float*)d_in[5];
    const float* b1ho = (const float*)d_in[6];
    const float* W2ho = (const float*)d_in[7];
    const float* b2ho = (const float*)d_in[8];
    float* out = (float*)d_out;

    dim3 grid(BATCH / EPB);   // 256 blocks x 128 threads = 1024 warps
    dim3 block(128);
    rnn_quad_kernel<<<grid, block>>>(inp, W1hh, b1hh, W2hh, b2hh,
                                     W1ho, b1ho, W2ho, b2ho, out);
}